// round 7
// baseline (speedup 1.0000x reference)
#include <cuda_runtime.h>
#include <cuda_bf16.h>
#include <cstdint>

// Single-query attention, B=4096, T=1024, D=64.
//   attn = softmax(mask_fill(q·k^T / 8, pad_mask, -1000))
//   out  = attn @ v
// Outputs: out [B,64] then attn [B,1024], concatenated (per out_size).
//
// Masked rows (score -1000 -> exp underflows to exact fp32 0, matching the
// reference) are never loaded: compacted index list halves K/V traffic.
//
// R7 change: groups walk CONTIGUOUS chunks of the compacted list instead of
// stride-16 — each warp's in-flight request stream stays in a narrow
// forward-moving address window (DRAM row-buffer locality), instead of
// hopping across the whole 256KB K region. Index list is padded to 16*c
// with a duplicate of row sh_idx[0] so phase-1 trip counts are warp-uniform
// (shuffle safety); padded rows get zero weight in phase 3.
//
// outp/qs4 carry __align__(16): accessed via float4*.

namespace {

constexpr int T_DIM = 1024;
constexpr int D_DIM = 64;
constexpr float INV_TEMP = 0.125f;   // 1/8
constexpr float MASK_FILL = -1000.0f;

__global__ __launch_bounds__(256, 8)
void sdpa_kernel(const float* __restrict__ q,
                 const float* __restrict__ k,
                 const float* __restrict__ v,
                 const int* __restrict__ mask,
                 float* __restrict__ out,
                 float* __restrict__ attn_out)
{
    const int b    = blockIdx.x;
    const int tid  = threadIdx.x;            // 0..255
    const int warp = tid >> 5;               // 0..7
    const int lane = tid & 31;

    __shared__ __align__(16) float4 qs4[D_DIM / 4];   // q row (256 B)
    __shared__ float  sc[T_DIM];             // scores -> probs (4 KB)
    __shared__ int    sh_idx[T_DIM];         // compacted active rows (4 KB)
    __shared__ int    sh_cnt;
    __shared__ float  red_max[8];
    __shared__ float  red_sum[8];
    __shared__ __align__(16) float outp[8][D_DIM];    // per-warp partials (2 KB)

    if (tid < D_DIM / 4) {
        qs4[tid] = reinterpret_cast<const float4*>(q + (size_t)b * D_DIM)[tid];
    }
    if (tid == 0) sh_cnt = 0;
    __syncthreads();

    const float4* __restrict__ k4 =
        reinterpret_cast<const float4*>(k + (size_t)b * T_DIM * D_DIM);
    const float4* __restrict__ v4 =
        reinterpret_cast<const float4*>(v + (size_t)b * T_DIM * D_DIM);
    const int* __restrict__ mrow = mask + (size_t)b * T_DIM;

    // ---- phase 0: prefill scores with MASK_FILL + compact unmasked rows ----
    #pragma unroll
    for (int base = warp * 128; base < warp * 128 + 128; base += 32) {
        const int t = base + lane;
        sc[t] = MASK_FILL;                           // default (masked) score
        const bool act = (mrow[t] == 0);
        const unsigned bal = __ballot_sync(0xffffffffu, act);
        int pos;
        if (lane == 0) pos = atomicAdd(&sh_cnt, __popc(bal));
        pos = __shfl_sync(0xffffffffu, pos, 0);
        if (act) {
            sh_idx[pos + __popc(bal & ((1u << lane) - 1u))] = t;
        }
    }
    __syncthreads();

    int nact = sh_cnt;
    const bool all_masked = (nact == 0);             // P ~ 2^-1024; still exact
    if (all_masked) {
        // uniform softmax over all rows: leave sc == MASK_FILL everywhere,
        // visit every V row.
        for (int t = tid; t < T_DIM; t += 256) sh_idx[t] = t;
        nact = T_DIM;
    }
    __syncthreads();

    // chunk size per group; pad index list to 16*c (<= 1024 always) with a
    // duplicate of a valid row so every group has a full, uniform range.
    const int c = (nact + 15) >> 4;
    {
        const int dup = sh_idx[0];
        for (int i = nact + tid; i < 16 * c; i += 256) sh_idx[i] = dup;
    }
    __syncthreads();

    // Warp layout: 16 lanes per row, 2 independent half-warp groups.
    const int half = lane >> 4;
    const int qi   = lane & 15;
    const float4 qv = qs4[qi];
    const int g = warp * 2 + half;                   // group id 0..15
    const int ibase = g * c;                         // contiguous chunk start

    // ---- phase 1: scores for ACTIVE rows (contiguous chunk walk) ----
    // Trip count c is warp-uniform; padded rows recompute sh_idx[0]'s score
    // (identical value) so the store needs no predicate.
    if (!all_masked) {
        #pragma unroll 4
        for (int j = 0; j < c; j++) {
            const int t = sh_idx[ibase + j];
            const float4 kv = k4[t * (D_DIM / 4) + qi];
            float p = kv.x * qv.x + kv.y * qv.y + kv.z * qv.z + kv.w * qv.w;
            p += __shfl_xor_sync(0xffffffffu, p, 1);
            p += __shfl_xor_sync(0xffffffffu, p, 2);
            p += __shfl_xor_sync(0xffffffffu, p, 4);
            p += __shfl_xor_sync(0xffffffffu, p, 8);
            if (qi == 0) sc[t] = p * INV_TEMP;
        }
    }
    __syncthreads();

    // ---- phase 2: softmax over all T (masked entries exp-underflow to 0) ----
    float mx = -1e30f;
    #pragma unroll
    for (int t = tid; t < T_DIM; t += 256) mx = fmaxf(mx, sc[t]);
    #pragma unroll
    for (int o = 16; o > 0; o >>= 1)
        mx = fmaxf(mx, __shfl_xor_sync(0xffffffffu, mx, o));
    if (lane == 0) red_max[warp] = mx;
    __syncthreads();

    float bm = red_max[0];
    #pragma unroll
    for (int i = 1; i < 8; i++) bm = fmaxf(bm, red_max[i]);

    float psum = 0.0f;
    #pragma unroll
    for (int t = tid; t < T_DIM; t += 256) {
        const float e = __expf(sc[t] - bm);
        sc[t] = e;
        psum += e;
    }
    #pragma unroll
    for (int o = 16; o > 0; o >>= 1)
        psum += __shfl_xor_sync(0xffffffffu, psum, o);
    if (lane == 0) red_sum[warp] = psum;
    __syncthreads();

    float tot = red_sum[0];
    #pragma unroll
    for (int i = 1; i < 8; i++) tot += red_sum[i];
    const float inv = 1.0f / tot;

    // normalize in shared; emit attn output (coalesced; masked -> exact 0)
    #pragma unroll
    for (int t = tid; t < T_DIM; t += 256) {
        const float pnorm = sc[t] * inv;
        sc[t] = pnorm;
        if (attn_out) attn_out[(size_t)b * T_DIM + t] = pnorm;
    }
    __syncthreads();

    // ---- phase 3: out[d] = sum over active rows of p[t]*v[t,d] ----
    // Padded entries (i >= nact) are duplicate rows: weight forced to 0.
    float4 acc = make_float4(0.f, 0.f, 0.f, 0.f);
    #pragma unroll 4
    for (int j = 0; j < c; j++) {
        const int i = ibase + j;
        const int t = sh_idx[i];
        const float p = (i < nact) ? sc[t] : 0.0f;
        const float4 vv = v4[t * (D_DIM / 4) + qi];
        acc.x += p * vv.x;
        acc.y += p * vv.y;
        acc.z += p * vv.z;
        acc.w += p * vv.w;
    }
    acc.x += __shfl_xor_sync(0xffffffffu, acc.x, 16);
    acc.y += __shfl_xor_sync(0xffffffffu, acc.y, 16);
    acc.z += __shfl_xor_sync(0xffffffffu, acc.z, 16);
    acc.w += __shfl_xor_sync(0xffffffffu, acc.w, 16);
    if (half == 0) {
        reinterpret_cast<float4*>(outp[warp])[qi] = acc;
    }
    __syncthreads();

    if (tid < D_DIM) {
        float s = 0.0f;
        #pragma unroll
        for (int w = 0; w < 8; w++) s += outp[w][tid];
        out[(size_t)b * D_DIM + tid] = s;
    }
}

} // namespace

extern "C" void kernel_launch(void* const* d_in, const int* in_sizes, int n_in,
                              void* d_out, int out_size)
{
    const float* q = (const float*)d_in[0];             // [B,64]
    const float* k = (const float*)d_in[1];             // [B,1024,64]
    const float* v = (const float*)d_in[2];             // [B,1024,64]
    const int*   mask = (const int*)d_in[3];            // [B,1024] bool->4B

    const int B = in_sizes[0] / D_DIM;                  // 4096

    float* out = (float*)d_out;                         // [B,64] first
    float* attn_out = nullptr;
    if (out_size > B * D_DIM) {
        attn_out = out + (size_t)B * D_DIM;             // [B,1024] second
    }

    sdpa_kernel<<<B, 256>>>(q, k, v, mask, out, attn_out);
}

// round 8
// speedup vs baseline: 1.0521x; 1.0521x over previous
#include <cuda_runtime.h>
#include <cuda_bf16.h>
#include <cstdint>

// Single-query attention, B=4096, T=1024, D=64.
//   attn = softmax(mask_fill(q·k^T / 8, pad_mask, -1000))
//   out  = attn @ v
// Outputs: out [B,64] then attn [B,1024], concatenated (per out_size).
//
// Masked rows (score -1000 -> exp underflows to exact fp32 0, matching the
// fp32 reference) are never loaded: compacted index list halves K/V traffic.
//
// Access pattern: stride-16 walk of the compacted list (R6) — the CTA's 16
// half-warp groups collectively cover a dense, forward-moving window of
// consecutive compacted indices, which the R7 experiment proved is what the
// DRAM system wants (contiguous per-group chunks regressed 182.7 -> 199).
//
// R8 delta vs R6: default caching instead of __ldcs (evict-first L2 policy
// gave no benefit on a zero-reuse stream and correlated with lower DRAM%).
//
// Phase-1 loop trip count is WARP-UNIFORM (pair-base iteration) because the
// body contains full-mask shuffles (R5 deadlock fix). outp/qs4 carry
// __align__(16): accessed via float4* (R4 crash fix).

namespace {

constexpr int T_DIM = 1024;
constexpr int D_DIM = 64;
constexpr float INV_TEMP = 0.125f;   // 1/8
constexpr float MASK_FILL = -1000.0f;

__global__ __launch_bounds__(256, 8)
void sdpa_kernel(const float* __restrict__ q,
                 const float* __restrict__ k,
                 const float* __restrict__ v,
                 const int* __restrict__ mask,
                 float* __restrict__ out,
                 float* __restrict__ attn_out)
{
    const int b    = blockIdx.x;
    const int tid  = threadIdx.x;            // 0..255
    const int warp = tid >> 5;               // 0..7
    const int lane = tid & 31;

    __shared__ __align__(16) float4 qs4[D_DIM / 4];   // q row (256 B)
    __shared__ float  sc[T_DIM];             // scores -> probs (4 KB)
    __shared__ int    sh_idx[T_DIM];         // compacted active rows (4 KB)
    __shared__ int    sh_cnt;
    __shared__ float  red_max[8];
    __shared__ float  red_sum[8];
    __shared__ __align__(16) float outp[8][D_DIM];    // per-warp partials (2 KB)

    if (tid < D_DIM / 4) {
        qs4[tid] = reinterpret_cast<const float4*>(q + (size_t)b * D_DIM)[tid];
    }
    if (tid == 0) sh_cnt = 0;
    __syncthreads();

    const float4* __restrict__ k4 =
        reinterpret_cast<const float4*>(k + (size_t)b * T_DIM * D_DIM);
    const float4* __restrict__ v4 =
        reinterpret_cast<const float4*>(v + (size_t)b * T_DIM * D_DIM);
    const int* __restrict__ mrow = mask + (size_t)b * T_DIM;

    // ---- phase 0: prefill scores with MASK_FILL + compact unmasked rows ----
    #pragma unroll
    for (int base = warp * 128; base < warp * 128 + 128; base += 32) {
        const int t = base + lane;
        sc[t] = MASK_FILL;                           // default (masked) score
        const bool act = (mrow[t] == 0);
        const unsigned bal = __ballot_sync(0xffffffffu, act);
        int pos;
        if (lane == 0) pos = atomicAdd(&sh_cnt, __popc(bal));
        pos = __shfl_sync(0xffffffffu, pos, 0);
        if (act) {
            sh_idx[pos + __popc(bal & ((1u << lane) - 1u))] = t;
        }
    }
    __syncthreads();

    int nact = sh_cnt;
    const bool all_masked = (nact == 0);             // P ~ 2^-1024; still exact
    if (all_masked) {
        // uniform softmax over all rows: leave sc == MASK_FILL everywhere,
        // visit every V row.
        for (int t = tid; t < T_DIM; t += 256) sh_idx[t] = t;
        nact = T_DIM;
    }
    __syncthreads();

    // Warp layout: 16 lanes per row, 2 rows (halves) per warp-iteration.
    const int half = lane >> 4;
    const int qi   = lane & 15;
    const float4 qv = qs4[qi];

    // ---- phase 1: scores for ACTIVE rows only ----
    // Warp-uniform trip count: loop over pair base i0; invalid half loads
    // a safe dummy row (sh_idx[i0], in-bounds) and suppresses its store.
    if (!all_masked) {
        #pragma unroll 4
        for (int i0 = warp * 2; i0 < nact; i0 += 16) {
            const int  i     = i0 + half;
            const bool valid = (i < nact);
            const int  t     = sh_idx[valid ? i : i0];
            const float4 kv = k4[t * (D_DIM / 4) + qi];
            float p = kv.x * qv.x + kv.y * qv.y + kv.z * qv.z + kv.w * qv.w;
            p += __shfl_xor_sync(0xffffffffu, p, 1);
            p += __shfl_xor_sync(0xffffffffu, p, 2);
            p += __shfl_xor_sync(0xffffffffu, p, 4);
            p += __shfl_xor_sync(0xffffffffu, p, 8);
            if (qi == 0 && valid) sc[t] = p * INV_TEMP;
        }
    }
    __syncthreads();

    // ---- phase 2: softmax over all T (masked entries exp-underflow to 0) ----
    float mx = -1e30f;
    #pragma unroll
    for (int t = tid; t < T_DIM; t += 256) mx = fmaxf(mx, sc[t]);
    #pragma unroll
    for (int o = 16; o > 0; o >>= 1)
        mx = fmaxf(mx, __shfl_xor_sync(0xffffffffu, mx, o));
    if (lane == 0) red_max[warp] = mx;
    __syncthreads();

    float bm = red_max[0];
    #pragma unroll
    for (int i = 1; i < 8; i++) bm = fmaxf(bm, red_max[i]);

    float psum = 0.0f;
    #pragma unroll
    for (int t = tid; t < T_DIM; t += 256) {
        const float e = __expf(sc[t] - bm);
        sc[t] = e;
        psum += e;
    }
    #pragma unroll
    for (int o = 16; o > 0; o >>= 1)
        psum += __shfl_xor_sync(0xffffffffu, psum, o);
    if (lane == 0) red_sum[warp] = psum;
    __syncthreads();

    float tot = red_sum[0];
    #pragma unroll
    for (int i = 1; i < 8; i++) tot += red_sum[i];
    const float inv = 1.0f / tot;

    // normalize in shared; emit attn output (coalesced; masked -> exact 0)
    #pragma unroll
    for (int t = tid; t < T_DIM; t += 256) {
        const float pnorm = sc[t] * inv;
        sc[t] = pnorm;
        if (attn_out) attn_out[(size_t)b * T_DIM + t] = pnorm;
    }
    __syncthreads();

    // ---- phase 3: out[d] = sum over ACTIVE rows of p[t] * v[t,d] ----
    // No shuffles inside this loop, so per-half bounds are deadlock-safe.
    const int g = warp * 2 + half;
    float4 acc = make_float4(0.f, 0.f, 0.f, 0.f);
    #pragma unroll 4
    for (int i = g; i < nact; i += 16) {
        const int t = sh_idx[i];
        const float p = sc[t];
        const float4 vv = v4[t * (D_DIM / 4) + qi];
        acc.x += p * vv.x;
        acc.y += p * vv.y;
        acc.z += p * vv.z;
        acc.w += p * vv.w;
    }
    acc.x += __shfl_xor_sync(0xffffffffu, acc.x, 16);
    acc.y += __shfl_xor_sync(0xffffffffu, acc.y, 16);
    acc.z += __shfl_xor_sync(0xffffffffu, acc.z, 16);
    acc.w += __shfl_xor_sync(0xffffffffu, acc.w, 16);
    if (half == 0) {
        reinterpret_cast<float4*>(outp[warp])[qi] = acc;
    }
    __syncthreads();

    if (tid < D_DIM) {
        float s = 0.0f;
        #pragma unroll
        for (int w = 0; w < 8; w++) s += outp[w][tid];
        out[(size_t)b * D_DIM + tid] = s;
    }
}

} // namespace

extern "C" void kernel_launch(void* const* d_in, const int* in_sizes, int n_in,
                              void* d_out, int out_size)
{
    const float* q = (const float*)d_in[0];             // [B,64]
    const float* k = (const float*)d_in[1];             // [B,1024,64]
    const float* v = (const float*)d_in[2];             // [B,1024,64]
    const int*   mask = (const int*)d_in[3];            // [B,1024] bool->4B

    const int B = in_sizes[0] / D_DIM;                  // 4096

    float* out = (float*)d_out;                         // [B,64] first
    float* attn_out = nullptr;
    if (out_size > B * D_DIM) {
        attn_out = out + (size_t)B * D_DIM;             // [B,1024] second
    }

    sdpa_kernel<<<B, 256>>>(q, k, v, mask, out, attn_out);
}

// round 9
// speedup vs baseline: 1.1163x; 1.0610x over previous
#include <cuda_runtime.h>
#include <cuda_bf16.h>
#include <cstdint>

// Single-query attention, B=4096, T=1024, D=64.
//   attn = softmax(mask_fill(q·k^T / 8, pad_mask, -1000))
//   out  = attn @ v
// Outputs: out [B,64] then attn [B,1024] (per out_size).
//
// Masked rows (score -1000 -> exp underflows to exact fp32 0, matching the
// fp32 reference) are never loaded: compacted index list halves K/V traffic.
//
// R9: 128-thread CTAs at 16 CTAs/SM (was 256 at 8). Same total threads/SM,
// but wave quantization improves: 4096 CTAs / 2368 concurrent = 1.73 waves
// with a 73%-full tail (vs 3.46 waves with a 46%-full tail) — the tail now
// stays above the DRAM saturation knee. Stride-8 group walk preserves the
// dense forward-moving window (R7 showed chunked walks regress). __ldcs
// restored (R8 showed removing it cost ~6us).
//
// Phase-1 trip count is WARP-UNIFORM (pair-base loop; R5 deadlock fix).
// outp/qs4 are __align__(16): accessed via float4* (R4 crash fix).

namespace {

constexpr int T_DIM = 1024;
constexpr int D_DIM = 64;
constexpr int NT    = 128;            // threads per CTA
constexpr int NW    = NT / 32;        // 4 warps
constexpr int NG    = NW * 2;         // 8 half-warp groups
constexpr float INV_TEMP = 0.125f;
constexpr float MASK_FILL = -1000.0f;

__global__ __launch_bounds__(NT, 16)
void sdpa_kernel(const float* __restrict__ q,
                 const float* __restrict__ k,
                 const float* __restrict__ v,
                 const int* __restrict__ mask,
                 float* __restrict__ out,
                 float* __restrict__ attn_out)
{
    const int b    = blockIdx.x;
    const int tid  = threadIdx.x;            // 0..127
    const int warp = tid >> 5;               // 0..3
    const int lane = tid & 31;

    __shared__ __align__(16) float4 qs4[D_DIM / 4];   // q row (256 B)
    __shared__ float  sc[T_DIM];             // scores -> probs (4 KB)
    __shared__ int    sh_idx[T_DIM];         // compacted active rows (4 KB)
    __shared__ int    sh_cnt;
    __shared__ float  red_max[NW];
    __shared__ float  red_sum[NW];
    __shared__ __align__(16) float outp[NW][D_DIM];   // per-warp partials (1 KB)

    if (tid < D_DIM / 4) {
        qs4[tid] = reinterpret_cast<const float4*>(q + (size_t)b * D_DIM)[tid];
    }
    if (tid == 0) sh_cnt = 0;
    __syncthreads();

    const float4* __restrict__ k4 =
        reinterpret_cast<const float4*>(k + (size_t)b * T_DIM * D_DIM);
    const float4* __restrict__ v4 =
        reinterpret_cast<const float4*>(v + (size_t)b * T_DIM * D_DIM);
    const int* __restrict__ mrow = mask + (size_t)b * T_DIM;

    // ---- phase 0: prefill scores with MASK_FILL + compact unmasked rows ----
    // warp w scans rows [w*256, (w+1)*256); coalesced 4B loads.
    #pragma unroll
    for (int base = warp * 256; base < warp * 256 + 256; base += 32) {
        const int t = base + lane;
        sc[t] = MASK_FILL;
        const bool act = (mrow[t] == 0);
        const unsigned bal = __ballot_sync(0xffffffffu, act);
        int pos;
        if (lane == 0) pos = atomicAdd(&sh_cnt, __popc(bal));
        pos = __shfl_sync(0xffffffffu, pos, 0);
        if (act) {
            sh_idx[pos + __popc(bal & ((1u << lane) - 1u))] = t;
        }
    }
    __syncthreads();

    int nact = sh_cnt;
    const bool all_masked = (nact == 0);             // P ~ 2^-1024; still exact
    if (all_masked) {
        for (int t = tid; t < T_DIM; t += NT) sh_idx[t] = t;
        nact = T_DIM;
    }
    __syncthreads();

    // Warp layout: 16 lanes per row, 2 rows (halves) per warp-iteration.
    const int half = lane >> 4;
    const int qi   = lane & 15;
    const float4 qv = qs4[qi];

    // ---- phase 1: scores for ACTIVE rows only (stride-NG dense window) ----
    if (!all_masked) {
        #pragma unroll 4
        for (int i0 = warp * 2; i0 < nact; i0 += NG) {
            const int  i     = i0 + half;
            const bool valid = (i < nact);
            const int  t     = sh_idx[valid ? i : i0];
            const float4 kv = __ldcs(&k4[t * (D_DIM / 4) + qi]);
            float p = kv.x * qv.x + kv.y * qv.y + kv.z * qv.z + kv.w * qv.w;
            p += __shfl_xor_sync(0xffffffffu, p, 1);
            p += __shfl_xor_sync(0xffffffffu, p, 2);
            p += __shfl_xor_sync(0xffffffffu, p, 4);
            p += __shfl_xor_sync(0xffffffffu, p, 8);
            if (qi == 0 && valid) sc[t] = p * INV_TEMP;
        }
    }
    __syncthreads();

    // ---- phase 2: softmax over all T (masked entries exp-underflow to 0) ----
    float mx = -1e30f;
    #pragma unroll
    for (int t = tid; t < T_DIM; t += NT) mx = fmaxf(mx, sc[t]);
    #pragma unroll
    for (int o = 16; o > 0; o >>= 1)
        mx = fmaxf(mx, __shfl_xor_sync(0xffffffffu, mx, o));
    if (lane == 0) red_max[warp] = mx;
    __syncthreads();

    float bm = red_max[0];
    #pragma unroll
    for (int i = 1; i < NW; i++) bm = fmaxf(bm, red_max[i]);

    float psum = 0.0f;
    #pragma unroll
    for (int t = tid; t < T_DIM; t += NT) {
        const float e = __expf(sc[t] - bm);
        sc[t] = e;
        psum += e;
    }
    #pragma unroll
    for (int o = 16; o > 0; o >>= 1)
        psum += __shfl_xor_sync(0xffffffffu, psum, o);
    if (lane == 0) red_sum[warp] = psum;
    __syncthreads();

    float tot = red_sum[0];
    #pragma unroll
    for (int i = 1; i < NW; i++) tot += red_sum[i];
    const float inv = 1.0f / tot;

    // normalize in shared; emit attn output (coalesced; masked -> exact 0)
    #pragma unroll
    for (int t = tid; t < T_DIM; t += NT) {
        const float pnorm = sc[t] * inv;
        sc[t] = pnorm;
        if (attn_out) attn_out[(size_t)b * T_DIM + t] = pnorm;
    }
    __syncthreads();

    // ---- phase 3: out[d] = sum over ACTIVE rows of p[t] * v[t,d] ----
    // No shuffles inside this loop, so per-half bounds are deadlock-safe.
    const int g = warp * 2 + half;
    float4 acc = make_float4(0.f, 0.f, 0.f, 0.f);
    #pragma unroll 4
    for (int i = g; i < nact; i += NG) {
        const int t = sh_idx[i];
        const float p = sc[t];
        const float4 vv = __ldcs(&v4[t * (D_DIM / 4) + qi]);
        acc.x += p * vv.x;
        acc.y += p * vv.y;
        acc.z += p * vv.z;
        acc.w += p * vv.w;
    }
    acc.x += __shfl_xor_sync(0xffffffffu, acc.x, 16);
    acc.y += __shfl_xor_sync(0xffffffffu, acc.y, 16);
    acc.z += __shfl_xor_sync(0xffffffffu, acc.z, 16);
    acc.w += __shfl_xor_sync(0xffffffffu, acc.w, 16);
    if (half == 0) {
        reinterpret_cast<float4*>(outp[warp])[qi] = acc;
    }
    __syncthreads();

    if (tid < D_DIM) {
        float s = 0.0f;
        #pragma unroll
        for (int w = 0; w < NW; w++) s += outp[w][tid];
        out[(size_t)b * D_DIM + tid] = s;
    }
}

} // namespace

extern "C" void kernel_launch(void* const* d_in, const int* in_sizes, int n_in,
                              void* d_out, int out_size)
{
    const float* q = (const float*)d_in[0];             // [B,64]
    const float* k = (const float*)d_in[1];             // [B,1024,64]
    const float* v = (const float*)d_in[2];             // [B,1024,64]
    const int*   mask = (const int*)d_in[3];            // [B,1024] bool->4B

    const int B = in_sizes[0] / D_DIM;                  // 4096

    float* out = (float*)d_out;                         // [B,64] first
    float* attn_out = nullptr;
    if (out_size > B * D_DIM) {
        attn_out = out + (size_t)B * D_DIM;             // [B,1024] second
    }

    sdpa_kernel<<<B, NT>>>(q, k, v, mask, out, attn_out);
}